// round 5
// baseline (speedup 1.0000x reference)
#include <cuda_runtime.h>
#include <cuda_bf16.h>

// Problem constants (fixed by reference_code)
#define HH 768
#define WW 768
#define BB 9
#define CC 3
#define NS 100          // N_SAMPLES
#define MM 13           // offsets with dy^2+dx^2 <= 4
#define DD 27           // PATCH*PATCH*C
#define DPAD 29         // padded stride (odd -> conflict-free vs 32 banks)
#define NPATCH (BB * MM)            // 117
#define NTHREADS 576                // 18 warps; 9 groups of 64 threads (2 warps) per batch b
#define NWARPS (NTHREADS / 32)
// scale = (1/T^2) / (K * B * NS) = 4 / (8*9*100); divide by counts[n] per block
#define BASE_SCALE (4.0f / (8.0f * 9.0f * 100.0f))

__device__ float        g_partials[NS];
__device__ unsigned int g_done = 0;    // completion counter; reset by last block each call

__device__ __constant__ int c_offy[MM] = {-2,-1,-1,-1, 0, 0, 0, 0, 0, 1, 1, 1, 2};
__device__ __constant__ int c_offx[MM] = { 0,-1, 0, 1,-2,-1, 0, 1, 2,-1, 0, 1, 0};

__global__ __launch_bounds__(NTHREADS)
void fused_kernel(const float* __restrict__ latents,
                  const int*   __restrict__ anchor_idx,
                  float*       __restrict__ out) {
    __shared__ float sh[NPATCH * DPAD];   // 117 RAW (unnormalized) patch vectors
    __shared__ float s_ss[NPATCH * 3];    // per-row sum-of-squares partials
    __shared__ float s_inv2[NPATCH];      // (1/max(||p||,eps))^2 per patch
    __shared__ int   s_valid[MM];
    __shared__ float s_wsum[NWARPS];
    __shared__ bool  s_is_last;

    const int n   = blockIdx.x;
    const int tid = threadIdx.x;
    const int a   = __ldg(&anchor_idx[n]);
    const int ay  = a / WW;
    const int ax  = a - ay * WW;

    if (tid < MM) {
        const int ny = ay + c_offy[tid];
        const int nx = ax + c_offx[tid];
        s_valid[tid] = (ny >= 0 && ny < HH && nx >= 0 && nx < WW) ? 1 : 0;
    }

    // --- Phase 1a: 351 threads, one per (patch, patch-row). Each loads 3 pixels
    //     (9 floats), writes raw values to shared, records partial sum-of-squares.
    if (tid < NPATCH * 3) {
        const int p = tid / 3;
        const int r = tid - p * 3;          // patch row 0..2 (ky = r-1)
        const int j = p / MM;
        const int m = p - j * MM;
        int py = ay + c_offy[m];
        int px = ax + c_offx[m];
        py = min(max(py, 0), HH - 1);       // matches jnp.clip on neighbor pos
        px = min(max(px, 0), WW - 1);
        const int yy = min(max(py + r - 1, 0), HH - 1);   // edge-pad clamp

        const float* rowp = latents + ((size_t)j * HH + yy) * (WW * CC);
        float* dst = &sh[p * DPAD + r * 9];
        float ss = 0.0f;
        #pragma unroll
        for (int kx = 0; kx < 3; kx++) {
            const int xx = min(max(px + kx - 1, 0), WW - 1);
            const float* pp = rowp + xx * CC;
            #pragma unroll
            for (int c = 0; c < CC; c++) {
                const float f = __ldg(pp + c);
                dst[kx * 3 + c] = f;
                ss += f * f;
            }
        }
        s_ss[tid] = ss;                     // tid == p*3 + r
    }
    __syncthreads();

    // --- Phase 1b: per-patch inverse-norm-squared (normalization deferred) ---
    if (tid < NPATCH) {
        const float ss = s_ss[3 * tid] + s_ss[3 * tid + 1] + s_ss[3 * tid + 2];
        const float inv = 1.0f / fmaxf(sqrtf(ss), 1e-12f);
        s_inv2[tid] = inv * inv;
    }
    __syncthreads();

    // --- Phase 2: each 64-thread group owns one batch b; anchor vector lives in
    //     registers (loaded via same-address smem broadcast, conflict-free).
    const int b = tid >> 6;                 // 0..8, uniform within each warp
    const int t = tid & 63;
    const int ap_idx = b * MM + 6;          // offset 6 == (0,0) == anchor patch
    const float* ap = &sh[ap_idx * DPAD];
    float av[DD];
    #pragma unroll
    for (int k = 0; k < DD; k++) av[k] = ap[k];
    const float wa = s_inv2[ap_idx];

    float acc = 0.0f;
    for (int rem = t; rem < NPATCH; rem += 64) {
        const int j = rem / MM;
        const int m = rem - j * MM;
        if (j == b || !s_valid[m]) continue;
        const float* nv = &sh[rem * DPAD];  // consecutive rows across lanes: conflict-free
        float d0 = 0.0f, d1 = 0.0f, d2 = 0.0f;
        #pragma unroll
        for (int k = 0; k < 9; k++) {
            d0 = fmaf(av[k],      nv[k],      d0);
            d1 = fmaf(av[k + 9],  nv[k + 9],  d1);
            d2 = fmaf(av[k + 18], nv[k + 18], d2);
        }
        const float d = (d0 + d1) + d2;
        acc += d * d * (wa * s_inv2[rem]);
    }

    // --- Block reduction (deterministic tree over 18 warps) ---
    #pragma unroll
    for (int o = 16; o > 0; o >>= 1)
        acc += __shfl_down_sync(0xFFFFFFFFu, acc, o);
    if ((tid & 31) == 0) s_wsum[tid >> 5] = acc;
    __syncthreads();

    if (tid == 0) {
        float s = 0.0f;
        #pragma unroll
        for (int w = 0; w < NWARPS; w++) s += s_wsum[w];
        int cnt = 0;
        #pragma unroll
        for (int m = 0; m < MM; m++) cnt += s_valid[m];
        g_partials[n] = s * (BASE_SCALE / (float)cnt);
        __threadfence();                       // partial visible before counter bump
        unsigned int prev = atomicAdd(&g_done, 1u);
        s_is_last = (prev == NS - 1);
    }
    __syncthreads();

    // --- Last block reduces all partials in fixed order (deterministic) ---
    if (s_is_last) {
        __threadfence();                       // acquire: see all partials
        if (tid < 32) {
            const volatile float* gp = g_partials;
            float tsum = 0.0f;
            for (int k = tid; k < NS; k += 32) tsum += gp[k];
            #pragma unroll
            for (int o = 16; o > 0; o >>= 1)
                tsum += __shfl_down_sync(0xFFFFFFFFu, tsum, o);
            if (tid == 0) {
                out[0] = tsum;
                g_done = 0;                    // reset for next graph replay
            }
        }
    }
}

extern "C" void kernel_launch(void* const* d_in, const int* in_sizes, int n_in,
                              void* d_out, int out_size) {
    const float* latents    = (const float*)d_in[0];
    const int*   anchor_idx = (const int*)d_in[1];
    float*       out        = (float*)d_out;

    fused_kernel<<<NS, NTHREADS>>>(latents, anchor_idx, out);
}

// round 6
// speedup vs baseline: 1.0029x; 1.0029x over previous
#include <cuda_runtime.h>
#include <cuda_bf16.h>

// Problem constants (fixed by reference_code)
#define HH 768
#define WW 768
#define BB 9
#define CC 3
#define NS 100          // N_SAMPLES
#define MM 13           // offsets with dy^2+dx^2 <= 4
#define DD 27           // PATCH*PATCH*C
#define DP 28           // padded stride: 28 floats = 7 float4, rows 16B-aligned
#define NPATCH (BB * MM)            // 117
#define NTHREADS 256                // 8 warps
// scale = (1/T^2) / (K * B * NS) = 4 / (8*9*100); divide by counts[n] per block
#define BASE_SCALE (4.0f / (8.0f * 9.0f * 100.0f))

__device__ float        g_partials[NS];
__device__ unsigned int g_done = 0;    // completion counter; reset by last block each call

__device__ __constant__ int c_offy[MM] = {-2,-1,-1,-1, 0, 0, 0, 0, 0, 1, 1, 1, 2};
__device__ __constant__ int c_offx[MM] = { 0,-1, 0, 1,-2,-1, 0, 1, 2,-1, 0, 1, 0};

__global__ __launch_bounds__(NTHREADS)
void fused_kernel(const float* __restrict__ latents,
                  const int*   __restrict__ anchor_idx,
                  float*       __restrict__ out) {
    __shared__ __align__(16) float sh[NPATCH * DP];  // 117 NORMALIZED patch vectors
    __shared__ int   s_valid[MM];
    __shared__ float s_wsum[NTHREADS / 32];

    const int tid  = threadIdx.x;
    const int n    = blockIdx.x;
    const int a    = __ldg(&anchor_idx[n]);
    const int ay   = a / WW;
    const int ax   = a - ay * WW;

    if (tid < MM) {
        const int ny = ay + c_offy[tid];
        const int nx = ax + c_offx[tid];
        s_valid[tid] = (ny >= 0 && ny < HH && nx >= 0 && nx < WW) ? 1 : 0;
    }

    // --- Phase 1: one thread per patch. 27 scattered LDG (independent, MLP=27),
    //     normalize in registers, store as 7 conflict-free STS.128 (pad word = 0).
    if (tid < NPATCH) {
        const int j = tid / MM;
        const int m = tid - j * MM;
        int py = ay + c_offy[m];
        int px = ax + c_offx[m];
        py = min(max(py, 0), HH - 1);        // matches jnp.clip on neighbor pos
        px = min(max(px, 0), WW - 1);

        const float* base = latents + (size_t)j * (HH * WW * CC);
        float v[DD];
        float ss = 0.0f;
        #pragma unroll
        for (int ky = -1; ky <= 1; ky++) {
            const int yy = min(max(py + ky, 0), HH - 1);     // edge-pad clamp
            #pragma unroll
            for (int kx = -1; kx <= 1; kx++) {
                const int xx = min(max(px + kx, 0), WW - 1);
                const float* p = base + ((size_t)yy * WW + xx) * CC;
                #pragma unroll
                for (int c = 0; c < CC; c++) {
                    const float f = __ldg(p + c);
                    v[((ky + 1) * 3 + (kx + 1)) * 3 + c] = f;
                    ss += f * f;
                }
            }
        }
        const float inv = 1.0f / fmaxf(sqrtf(ss), 1e-12f);
        float4* dst = (float4*)&sh[tid * DP];
        #pragma unroll
        for (int q = 0; q < 6; q++)
            dst[q] = make_float4(v[4*q]*inv, v[4*q+1]*inv, v[4*q+2]*inv, v[4*q+3]*inv);
        dst[6] = make_float4(v[24]*inv, v[25]*inv, v[26]*inv, 0.0f);
    }
    __syncthreads();

    // --- Phase 2: lane = one neighbor vector cached in registers (7x LDS.128,
    //     conflict-free: stride 7 float4s, 7l mod 8 distinct). Anchors stream in
    //     as broadcast LDS.128 (uniform address = 1 crossbar cycle / 4 words).
    //     Warps 0-3 cover neighbors for b=0..3; warps 4-7 for b=4..8.
    const int w     = tid >> 5;
    const int lane  = tid & 31;
    const int chunk = w & 3;                 // 4 chunks x 32 lanes >= 117
    const int p     = chunk * 32 + lane;     // neighbor (j,m) index
    const bool have = (p < NPATCH);
    const int pp    = have ? p : 0;
    const int j     = pp / MM;
    const int m     = pp - j * MM;
    const bool ok   = have && (s_valid[m] != 0);

    float4 v4[7];
    {
        const float4* vr = (const float4*)&sh[pp * DP];
        #pragma unroll
        for (int q = 0; q < 7; q++) v4[q] = vr[q];
    }

    const int b0 = (w < 4) ? 0 : 4;
    const int b1 = (w < 4) ? 4 : 9;
    float acc = 0.0f;
    for (int b = b0; b < b1; b++) {
        const float4* ar = (const float4*)&sh[(b * MM + 6) * DP]; // anchor = offset (0,0)
        float d0 = 0.0f, d1 = 0.0f, d2 = 0.0f, d3 = 0.0f;
        #pragma unroll
        for (int q = 0; q < 7; q++) {
            const float4 a4 = ar[q];         // broadcast: uniform address in warp
            d0 = fmaf(a4.x, v4[q].x, d0);
            d1 = fmaf(a4.y, v4[q].y, d1);
            d2 = fmaf(a4.z, v4[q].z, d2);
            d3 = fmaf(a4.w, v4[q].w, d3);    // pad lane: 0*0
        }
        const float d = (d0 + d1) + (d2 + d3);
        if (ok && j != b) acc += d * d;
    }

    // --- Block reduction (deterministic tree over 8 warps) ---
    #pragma unroll
    for (int o = 16; o > 0; o >>= 1)
        acc += __shfl_down_sync(0xFFFFFFFFu, acc, o);
    if (lane == 0) s_wsum[w] = acc;
    __syncthreads();

    // --- Publish partial with a release-increment; last block (acquire) reduces.
    //     Confined to warp 0: no extra __syncthreads / smem broadcast needed.
    if (w == 0) {
        unsigned int prev = 0;
        if (lane == 0) {
            float s = 0.0f;
            #pragma unroll
            for (int k = 0; k < NTHREADS / 32; k++) s += s_wsum[k];
            int cnt = 0;
            #pragma unroll
            for (int mm = 0; mm < MM; mm++) cnt += s_valid[mm];
            g_partials[n] = s * (BASE_SCALE / (float)cnt);
            // acq_rel: release publishes g_partials[n]; acquire (on the final
            // increment) makes every released partial visible to this thread.
            asm volatile("atom.acq_rel.gpu.add.u32 %0, [%1], %2;"
                         : "=r"(prev) : "l"(&g_done), "r"(1u) : "memory");
        }
        prev = __shfl_sync(0xFFFFFFFFu, prev, 0);
        if (prev == NS - 1) {
            const volatile float* gp = g_partials;
            float t = 0.0f;
            for (int k = lane; k < NS; k += 32) t += gp[k];   // fixed-order lanes
            #pragma unroll
            for (int o = 16; o > 0; o >>= 1)
                t += __shfl_down_sync(0xFFFFFFFFu, t, o);
            if (lane == 0) {
                out[0] = t;
                g_done = 0;                  // reset for next graph replay
            }
        }
    }
}

extern "C" void kernel_launch(void* const* d_in, const int* in_sizes, int n_in,
                              void* d_out, int out_size) {
    const float* latents    = (const float*)d_in[0];
    const int*   anchor_idx = (const int*)d_in[1];
    float*       out        = (float*)d_out;

    fused_kernel<<<NS, NTHREADS>>>(latents, anchor_idx, out);
}

// round 7
// speedup vs baseline: 1.2294x; 1.2258x over previous
#include <cuda_runtime.h>
#include <cuda_bf16.h>

// Problem constants (fixed by reference_code)
#define HH 768
#define WW 768
#define BB 9
#define CC 3
#define NS 100          // N_SAMPLES
#define MM 13           // offsets with dy^2+dx^2 <= 4
#define DD 27           // PATCH*PATCH*C
#define DP 28           // padded stride: 28 floats = 7 float4, rows 16B-aligned
#define NPATCH (BB * MM)            // 117
#define NTHREADS 256                // 8 warps
// scale = (1/T^2) / (K * B * NS) = 4 / (8*9*100); divide by counts[n] per block
#define BASE_SCALE (4.0f / (8.0f * 9.0f * 100.0f))

// Fixed-point accumulation: partial * 2^44 rounded to integer. Integer adds
// commute -> bit-deterministic total regardless of block arrival order.
#define FIX_SCALE   1.7592186044416e13f      // 2^44
#define FIX_INV     5.684341886080802e-14    // 2^-44 (double)

// Nibble-packed offsets (value+2 in 4 bits at position 4*m), pure-ALU decode:
// offy: -2,-1,-1,-1, 0, 0, 0, 0, 0, 1, 1, 1, 2
// offx:  0,-1, 0, 1,-2,-1, 0, 1, 2,-1, 0, 1, 0
#define OY_PACK 0x4333222221110ULL
#define OX_PACK 0x2321432103212ULL
#define OFFY(m) ((int)((OY_PACK >> (4 * (m))) & 15ULL) - 2)
#define OFFX(m) ((int)((OX_PACK >> (4 * (m))) & 15ULL) - 2)

__device__ unsigned long long g_sum  = 0ULL;  // fixed-point loss accumulator
__device__ unsigned int       g_done = 0;     // completion counter

__global__ __launch_bounds__(NTHREADS)
void fused_kernel(const float* __restrict__ latents,
                  const int*   __restrict__ anchor_idx,
                  float*       __restrict__ out) {
    __shared__ __align__(16) float sh[NPATCH * DP];  // 117 NORMALIZED patch vectors
    __shared__ int   s_valid[MM];
    __shared__ float s_wsum[NTHREADS / 32];

    const int tid  = threadIdx.x;
    const int n    = blockIdx.x;
    const int a    = __ldg(&anchor_idx[n]);
    const int ay   = a / WW;
    const int ax   = a - ay * WW;

    if (tid < MM) {
        const int ny = ay + OFFY(tid);
        const int nx = ax + OFFX(tid);
        s_valid[tid] = (ny >= 0 && ny < HH && nx >= 0 && nx < WW) ? 1 : 0;
    }

    // --- Phase 1: one thread per patch. 27 scattered LDG (independent, MLP=27),
    //     normalize in registers, store as 7 conflict-free STS.128 (pad word = 0).
    if (tid < NPATCH) {
        const int j = tid / MM;
        const int m = tid - j * MM;
        int py = ay + OFFY(m);
        int px = ax + OFFX(m);
        py = min(max(py, 0), HH - 1);        // matches jnp.clip on neighbor pos
        px = min(max(px, 0), WW - 1);

        const float* base = latents + (size_t)j * (HH * WW * CC);
        float v[DD];
        float ss = 0.0f;
        #pragma unroll
        for (int ky = -1; ky <= 1; ky++) {
            const int yy = min(max(py + ky, 0), HH - 1);     // edge-pad clamp
            #pragma unroll
            for (int kx = -1; kx <= 1; kx++) {
                const int xx = min(max(px + kx, 0), WW - 1);
                const float* p = base + ((size_t)yy * WW + xx) * CC;
                #pragma unroll
                for (int c = 0; c < CC; c++) {
                    const float f = __ldg(p + c);
                    v[((ky + 1) * 3 + (kx + 1)) * 3 + c] = f;
                    ss += f * f;
                }
            }
        }
        const float inv = 1.0f / fmaxf(sqrtf(ss), 1e-12f);
        float4* dst = (float4*)&sh[tid * DP];
        #pragma unroll
        for (int q = 0; q < 6; q++)
            dst[q] = make_float4(v[4*q]*inv, v[4*q+1]*inv, v[4*q+2]*inv, v[4*q+3]*inv);
        dst[6] = make_float4(v[24]*inv, v[25]*inv, v[26]*inv, 0.0f);
    }
    __syncthreads();

    // --- Phase 2: lane = one neighbor vector cached in registers (7x LDS.128,
    //     conflict-free). Anchors stream in as broadcast LDS.128 (uniform
    //     address). Warps 0-3 cover b=0..3; warps 4-7 cover b=4..8.
    const int w     = tid >> 5;
    const int lane  = tid & 31;
    const int chunk = w & 3;                 // 4 chunks x 32 lanes >= 117
    const int p     = chunk * 32 + lane;     // neighbor (j,m) index
    const bool have = (p < NPATCH);
    const int pp    = have ? p : 0;
    const int j     = pp / MM;
    const int m     = pp - j * MM;
    const bool ok   = have && (s_valid[m] != 0);

    float4 v4[7];
    {
        const float4* vr = (const float4*)&sh[pp * DP];
        #pragma unroll
        for (int q = 0; q < 7; q++) v4[q] = vr[q];
    }

    const int b0 = (w < 4) ? 0 : 4;
    const int b1 = (w < 4) ? 4 : 9;
    float acc = 0.0f;
    for (int b = b0; b < b1; b++) {
        const float4* ar = (const float4*)&sh[(b * MM + 6) * DP]; // anchor = offset (0,0)
        float d0 = 0.0f, d1 = 0.0f, d2 = 0.0f, d3 = 0.0f;
        #pragma unroll
        for (int q = 0; q < 7; q++) {
            const float4 a4 = ar[q];         // broadcast: uniform address in warp
            d0 = fmaf(a4.x, v4[q].x, d0);
            d1 = fmaf(a4.y, v4[q].y, d1);
            d2 = fmaf(a4.z, v4[q].z, d2);
            d3 = fmaf(a4.w, v4[q].w, d3);    // pad lane: 0*0
        }
        const float d = (d0 + d1) + (d2 + d3);
        if (ok && j != b) acc += d * d;
    }

    // --- Block reduction (deterministic tree over 8 warps) ---
    #pragma unroll
    for (int o = 16; o > 0; o >>= 1)
        acc += __shfl_down_sync(0xFFFFFFFFu, acc, o);
    if (lane == 0) s_wsum[w] = acc;
    __syncthreads();

    // --- Tail: fixed-point atomic accumulation (deterministic), then a
    //     release-increment on the counter; last block converts and resets.
    if (w == 0) {
        unsigned int prev = 0;
        if (lane == 0) {
            float s = 0.0f;
            #pragma unroll
            for (int k = 0; k < NTHREADS / 32; k++) s += s_wsum[k];
            int cnt = 0;
            #pragma unroll
            for (int mm = 0; mm < MM; mm++) cnt += s_valid[mm];
            const float partial = s * (BASE_SCALE / (float)cnt);  // >= 0
            const long long q = __float2ll_rn(partial * FIX_SCALE);
            atomicAdd(&g_sum, (unsigned long long)q);
            // acq_rel: release publishes the g_sum add; acquire on the final
            // increment makes every prior add visible to this thread.
            asm volatile("atom.acq_rel.gpu.add.u32 %0, [%1], %2;"
                         : "=r"(prev) : "l"(&g_done), "r"(1u) : "memory");
            if (prev == NS - 1) {
                const unsigned long long total =
                    *(volatile unsigned long long*)&g_sum;
                out[0] = (float)((double)total * FIX_INV);
                g_sum  = 0ULL;               // reset for next graph replay
                g_done = 0;
            }
        }
    }
}

extern "C" void kernel_launch(void* const* d_in, const int* in_sizes, int n_in,
                              void* d_out, int out_size) {
    const float* latents    = (const float*)d_in[0];
    const int*   anchor_idx = (const int*)d_in[1];
    float*       out        = (float*)d_out;

    fused_kernel<<<NS, NTHREADS>>>(latents, anchor_idx, out);
}